// round 1
// baseline (speedup 1.0000x reference)
#include <cuda_runtime.h>
#include <cuda_bf16.h>
#include <cstdint>
#include <math.h>

#define N_NODES 40000
#define N_EDGES 160000
#define DIN 64
#define D 32
#define EIN 16
#define EH 128
#define STEPS 3
#define EPS_BN 1e-5f

// ---------------- device scratch (no allocation allowed) ----------------
__device__ float g_h[N_NODES * D];          // node features / GRU hidden (5.12 MB)
__device__ float g_eh[N_EDGES * EH];        // edge hidden (82 MB)
__device__ float g_theta[(size_t)N_EDGES * D * D]; // per-edge weight mats (655 MB)
__device__ float g_agg[N_NODES * D];        // scatter-add accumulator (5.12 MB)

// ---------------- helpers ----------------
__device__ __forceinline__ float cvt_tf32(float x) {
    uint32_t u;
    asm("cvt.rna.tf32.f32 %0, %1;" : "=r"(u) : "f"(x));
    return __uint_as_float(u);
}

__device__ __forceinline__ void mma_tf32_16x8x8(float c[4], const uint32_t a[4],
                                                uint32_t b0, uint32_t b1) {
    asm volatile(
        "mma.sync.aligned.m16n8k8.row.col.f32.tf32.tf32.f32 "
        "{%0,%1,%2,%3}, {%4,%5,%6,%7}, {%8,%9}, {%0,%1,%2,%3};"
        : "+f"(c[0]), "+f"(c[1]), "+f"(c[2]), "+f"(c[3])
        : "r"(a[0]), "r"(a[1]), "r"(a[2]), "r"(a[3]), "r"(b0), "r"(b1));
}

// ---------------- K1: h = relu(bn(x @ proj_W + proj_b)) ----------------
__global__ void __launch_bounds__(256) k_proj(const float* __restrict__ x,
                                              const float* __restrict__ W,
                                              const float* __restrict__ b,
                                              const float* __restrict__ g,
                                              const float* __restrict__ bb) {
    __shared__ float Ws[DIN * D]; // [64][32]
    int tid = threadIdx.x;
    for (int i = tid; i < DIN * D; i += 256) Ws[i] = W[i];
    __syncthreads();
    int lane = tid & 31;
    int node = blockIdx.x * 8 + (tid >> 5);
    if (node >= N_NODES) return;
    float x0 = x[node * DIN + lane];
    float x1 = x[node * DIN + 32 + lane];
    float acc = 0.f;
#pragma unroll
    for (int i = 0; i < 32; i++) {
        acc = fmaf(__shfl_sync(0xffffffffu, x0, i), Ws[i * D + lane], acc);
        acc = fmaf(__shfl_sync(0xffffffffu, x1, i), Ws[(32 + i) * D + lane], acc);
    }
    float s = g[lane] * rsqrtf(1.f + EPS_BN);
    float v = (acc + b[lane]) * s + bb[lane];
    g_h[node * D + lane] = fmaxf(v, 0.f);
}

// ---------------- K2: eh = relu(bn(edge_attr @ eW1 + eb1)) ----------------
__global__ void __launch_bounds__(256) k_edgehidden(const float* __restrict__ ea,
                                                    const float* __restrict__ W1,
                                                    const float* __restrict__ b1,
                                                    const float* __restrict__ g,
                                                    const float* __restrict__ bb) {
    __shared__ float W1s[EIN * EH]; // [16][128]
    __shared__ float eas[2][EIN];
    int tid = threadIdx.x;
    for (int i = tid; i < EIN * EH; i += 256) W1s[i] = W1[i];
    int e0 = blockIdx.x * 2;
    if (tid < 32) eas[tid >> 4][tid & 15] = ea[e0 * EIN + tid];
    __syncthreads();
    int el = tid >> 7;       // 0..1
    int k = tid & 127;       // 0..127
    int e = e0 + el;
    float acc = 0.f;
#pragma unroll
    for (int i = 0; i < EIN; i++) acc = fmaf(eas[el][i], W1s[i * EH + k], acc);
    float s = g[k] * rsqrtf(1.f + EPS_BN);
    float v = (acc + b1[k]) * s + bb[k];
    g_eh[(size_t)e * EH + k] = fmaxf(v, 0.f);
}

// ---------------- K3: theta = eh @ eW2 + eb2 (tf32 MMA) ----------------
// M=160000, N=1024, K=128. Block tile 128x128, K fully resident in smem.
// 256 threads = 8 warps (4 m x 2 n), warp tile 32x64.
#define AS_LD 132
#define BS_LD 136
#define GEMM_SMEM ((128 * AS_LD + 128 * BS_LD) * 4)

__global__ void __launch_bounds__(256) k_theta(const float* __restrict__ eW2,
                                               const float* __restrict__ eb2) {
    extern __shared__ float smem[];
    float* As = smem;               // [128][AS_LD]
    float* Bs = smem + 128 * AS_LD; // [128][BS_LD]
    const int tid = threadIdx.x;
    const int m0 = blockIdx.y * 128;
    const int n0 = blockIdx.x * 128;

    {
        int r = tid >> 5;
        int c4 = (tid & 31) * 4;
#pragma unroll
        for (int it = 0; it < 16; it++) {
            int row = r + it * 8;
            float4 v = *reinterpret_cast<const float4*>(&g_eh[(size_t)(m0 + row) * EH + c4]);
            v.x = cvt_tf32(v.x); v.y = cvt_tf32(v.y); v.z = cvt_tf32(v.z); v.w = cvt_tf32(v.w);
            *reinterpret_cast<float4*>(&As[row * AS_LD + c4]) = v;
        }
#pragma unroll
        for (int it = 0; it < 16; it++) {
            int row = r + it * 8; // k
            float4 v = *reinterpret_cast<const float4*>(&eW2[(size_t)row * 1024 + n0 + c4]);
            v.x = cvt_tf32(v.x); v.y = cvt_tf32(v.y); v.z = cvt_tf32(v.z); v.w = cvt_tf32(v.w);
            *reinterpret_cast<float4*>(&Bs[row * BS_LD + c4]) = v;
        }
    }
    __syncthreads();

    const int warp = tid >> 5, lane = tid & 31;
    const int wm = (warp & 3) * 32;
    const int wn = (warp >> 2) * 64;
    const int lq = lane >> 2;  // 0..7
    const int lr = lane & 3;   // 0..3

    float c[2][8][4];
#pragma unroll
    for (int mt = 0; mt < 2; mt++)
#pragma unroll
        for (int nt = 0; nt < 8; nt++)
#pragma unroll
            for (int i = 0; i < 4; i++) c[mt][nt][i] = 0.f;

#pragma unroll
    for (int ks = 0; ks < 16; ks++) {
        int k0 = ks * 8;
        uint32_t a[2][4];
#pragma unroll
        for (int mt = 0; mt < 2; mt++) {
            int row = wm + mt * 16 + lq;
            int col = k0 + lr;
            a[mt][0] = __float_as_uint(As[row * AS_LD + col]);
            a[mt][1] = __float_as_uint(As[(row + 8) * AS_LD + col]);
            a[mt][2] = __float_as_uint(As[row * AS_LD + col + 4]);
            a[mt][3] = __float_as_uint(As[(row + 8) * AS_LD + col + 4]);
        }
#pragma unroll
        for (int nt = 0; nt < 8; nt++) {
            int colB = wn + nt * 8 + lq;
            uint32_t b0 = __float_as_uint(Bs[(k0 + lr) * BS_LD + colB]);
            uint32_t b1 = __float_as_uint(Bs[(k0 + 4 + lr) * BS_LD + colB]);
            mma_tf32_16x8x8(c[0][nt], a[0], b0, b1);
            mma_tf32_16x8x8(c[1][nt], a[1], b0, b1);
        }
    }

    // epilogue: + eb2, store fp32
#pragma unroll
    for (int mt = 0; mt < 2; mt++) {
#pragma unroll
        for (int nt = 0; nt < 8; nt++) {
            int row = m0 + wm + mt * 16 + lq;
            int col = n0 + wn + nt * 8 + lr * 2;
            float bv0 = eb2[col], bv1 = eb2[col + 1];
            float2 v01 = make_float2(c[mt][nt][0] + bv0, c[mt][nt][1] + bv1);
            float2 v23 = make_float2(c[mt][nt][2] + bv0, c[mt][nt][3] + bv1);
            *reinterpret_cast<float2*>(&g_theta[(size_t)row * 1024 + col]) = v01;
            *reinterpret_cast<float2*>(&g_theta[(size_t)(row + 8) * 1024 + col]) = v23;
        }
    }
}

// ---------------- K4: zero agg ----------------
__global__ void k_zero() {
    int i = blockIdx.x * blockDim.x + threadIdx.x;
    if (i < N_NODES * D) g_agg[i] = 0.f;
}

// ---------------- K5: msg = h[src] @ theta_e ; atomic scatter to agg[dst] ----
__global__ void __launch_bounds__(256) k_msg(const int* __restrict__ ei) {
    int gw = (blockIdx.x * blockDim.x + threadIdx.x) >> 5;
    if (gw >= N_EDGES) return;
    int lane = threadIdx.x & 31;
    int src = ei[gw];
    int dst = ei[N_EDGES + gw];
    float hv = g_h[src * D + lane];
    const float* th = g_theta + (size_t)gw * (D * D);
    float acc = 0.f;
#pragma unroll
    for (int i = 0; i < 32; i += 8) {
        float t0 = th[(i + 0) * 32 + lane];
        float t1 = th[(i + 1) * 32 + lane];
        float t2 = th[(i + 2) * 32 + lane];
        float t3 = th[(i + 3) * 32 + lane];
        float t4 = th[(i + 4) * 32 + lane];
        float t5 = th[(i + 5) * 32 + lane];
        float t6 = th[(i + 6) * 32 + lane];
        float t7 = th[(i + 7) * 32 + lane];
        acc = fmaf(__shfl_sync(0xffffffffu, hv, i + 0), t0, acc);
        acc = fmaf(__shfl_sync(0xffffffffu, hv, i + 1), t1, acc);
        acc = fmaf(__shfl_sync(0xffffffffu, hv, i + 2), t2, acc);
        acc = fmaf(__shfl_sync(0xffffffffu, hv, i + 3), t3, acc);
        acc = fmaf(__shfl_sync(0xffffffffu, hv, i + 4), t4, acc);
        acc = fmaf(__shfl_sync(0xffffffffu, hv, i + 5), t5, acc);
        acc = fmaf(__shfl_sync(0xffffffffu, hv, i + 6), t6, acc);
        acc = fmaf(__shfl_sync(0xffffffffu, hv, i + 7), t7, acc);
    }
    atomicAdd(&g_agg[dst * D + lane], acc);
}

// ---------------- K6: conv + relu + GRU cell, in-place on g_h ----------------
__global__ void __launch_bounds__(256) k_update(const float* __restrict__ root,
                                                const float* __restrict__ cb,
                                                const float* __restrict__ W_ih,
                                                const float* __restrict__ W_hh,
                                                const float* __restrict__ b_ih,
                                                const float* __restrict__ b_hh,
                                                float* __restrict__ out,
                                                int write_out) {
    __shared__ float s_wih[D * 96]; // transposed [i][j]
    __shared__ float s_whh[D * 96];
    __shared__ float s_root[D * D];
    __shared__ float s_bih[96], s_bhh[96], s_cb[D];
    int tid = threadIdx.x;
    for (int idx = tid; idx < 96 * D; idx += 256) {
        int j = idx / D, i = idx % D;
        s_wih[i * 96 + j] = W_ih[idx];
        s_whh[i * 96 + j] = W_hh[idx];
    }
    for (int idx = tid; idx < D * D; idx += 256) s_root[idx] = root[idx];
    if (tid < 96) { s_bih[tid] = b_ih[tid]; s_bhh[tid] = b_hh[tid]; }
    if (tid < D) s_cb[tid] = cb[tid];
    __syncthreads();

    int lane = tid & 31;
    int v = blockIdx.x * 8 + (tid >> 5);
    if (v >= N_NODES) return;

    float hv = g_h[v * D + lane];
    float conv = g_agg[v * D + lane] + s_cb[lane];
#pragma unroll
    for (int i = 0; i < 32; i++)
        conv = fmaf(__shfl_sync(0xffffffffu, hv, i), s_root[i * D + lane], conv);
    float m = fmaxf(conv, 0.f);

    float gr = s_bih[lane], gz = s_bih[32 + lane], gn = s_bih[64 + lane];
    float hr = s_bhh[lane], hz = s_bhh[32 + lane], hn = s_bhh[64 + lane];
#pragma unroll
    for (int i = 0; i < 32; i++) {
        float mi = __shfl_sync(0xffffffffu, m, i);
        float hi = __shfl_sync(0xffffffffu, hv, i);
        const float* wi = &s_wih[i * 96];
        const float* wh = &s_whh[i * 96];
        gr = fmaf(mi, wi[lane], gr);
        gz = fmaf(mi, wi[32 + lane], gz);
        gn = fmaf(mi, wi[64 + lane], gn);
        hr = fmaf(hi, wh[lane], hr);
        hz = fmaf(hi, wh[32 + lane], hz);
        hn = fmaf(hi, wh[64 + lane], hn);
    }
    float r = 1.f / (1.f + expf(-(gr + hr)));
    float z = 1.f / (1.f + expf(-(gz + hz)));
    float n = tanhf(gn + r * hn);
    float hnew = (1.f - z) * n + z * hv;
    g_h[v * D + lane] = hnew;
    if (write_out) out[v * D + lane] = hnew;
}

// ---------------- launch ----------------
extern "C" void kernel_launch(void* const* d_in, const int* in_sizes, int n_in,
                              void* d_out, int out_size) {
    (void)in_sizes; (void)n_in; (void)out_size;
    const float* x        = (const float*)d_in[0];
    const int*   ei       = (const int*)d_in[1];
    const float* ea       = (const float*)d_in[2];
    const float* proj_W   = (const float*)d_in[3];
    const float* proj_b   = (const float*)d_in[4];
    const float* bn1_g    = (const float*)d_in[5];
    const float* bn1_b    = (const float*)d_in[6];
    const float* eW1      = (const float*)d_in[7];
    const float* eb1      = (const float*)d_in[8];
    const float* bn2_g    = (const float*)d_in[9];
    const float* bn2_b    = (const float*)d_in[10];
    const float* eW2      = (const float*)d_in[11];
    const float* eb2      = (const float*)d_in[12];
    const float* root     = (const float*)d_in[13];
    const float* cb       = (const float*)d_in[14];
    const float* W_ih     = (const float*)d_in[15];
    const float* W_hh     = (const float*)d_in[16];
    const float* b_ih     = (const float*)d_in[17];
    const float* b_hh     = (const float*)d_in[18];
    float* out = (float*)d_out;

    k_proj<<<N_NODES / 8, 256>>>(x, proj_W, proj_b, bn1_g, bn1_b);
    k_edgehidden<<<N_EDGES / 2, 256>>>(ea, eW1, eb1, bn2_g, bn2_b);

    static int smem_set = 0;
    if (!smem_set) {
        cudaFuncSetAttribute(k_theta, cudaFuncAttributeMaxDynamicSharedMemorySize, GEMM_SMEM);
        smem_set = 1;
    }
    dim3 tgrid(1024 / 128, N_EDGES / 128); // (8, 1250)
    k_theta<<<tgrid, 256, GEMM_SMEM>>>(eW2, eb2);

    for (int s = 0; s < STEPS; s++) {
        k_zero<<<(N_NODES * D + 255) / 256, 256>>>();
        k_msg<<<(N_EDGES * 32) / 256, 256>>>(ei);
        k_update<<<N_NODES / 8, 256>>>(root, cb, W_ih, W_hh, b_ih, b_hh,
                                       out, s == STEPS - 1 ? 1 : 0);
    }
}